// round 7
// baseline (speedup 1.0000x reference)
#include <cuda_runtime.h>

// Problem constants
#define NB    16
#define HW    (544*960)          // 522240 gray pixels per batch
#define HW4   (HW/4)             // 130560 float4 per channel per batch
#define TPB   256
#define BPB   51                 // blocks per batch
#define ITERS (HW4/(TPB*BPB))    // 10 (exact: 130560 = 256*51*10)
#define NPART (NB*BPB)           // 816

// Partial accumulators — every slot written every launch (no zeroing needed)
__device__ float g_psum[NPART];
__device__ int   g_pbright[NPART];
__device__ int   g_pdark[NPART];
__device__ int   g_ticket_b[NB];   // per-batch tickets; reset by each batch finalizer

__global__ __launch_bounds__(TPB, 6) void fused_kernel(const float* __restrict__ img,
                                                       const float* __restrict__ e1in,
                                                       const float* __restrict__ e2in,
                                                       float* __restrict__ out) {
    const int blk   = blockIdx.x;
    const int batch = blk / BPB;
    const int bpos  = blk % BPB;

    const float4* __restrict__ c0 = (const float4*)(img + (size_t)batch * 3 * HW);
    const float4* __restrict__ c1 = c0 + HW4;
    const float4* __restrict__ c2 = c1 + HW4;

    const int base = bpos * (TPB * ITERS) + threadIdx.x;

    float sum = 0.0f;          // sum of (r+g+b); divide by 3*HW at the end
    int nb = 0, nd = 0;

    // 2-deep software pipeline: keep next iteration's 3 loads in flight
    float4 a0 = __ldcs(c0 + base);
    float4 b0 = __ldcs(c1 + base);
    float4 v0 = __ldcs(c2 + base);

    #pragma unroll
    for (int i = 0; i < ITERS; i++) {
        float4 a1, b1, v1;
        if (i + 1 < ITERS) {
            const int nidx = base + (i + 1) * TPB;
            a1 = __ldcs(c0 + nidx);
            b1 = __ldcs(c1 + nidx);
            v1 = __ldcs(c2 + nidx);
        }

        float t0 = a0.x + b0.x + v0.x;
        float t1 = a0.y + b0.y + v0.y;
        float t2 = a0.z + b0.z + v0.z;
        float t3 = a0.w + b0.w + v0.w;

        sum += t0 + t1 + t2 + t3;
        // gray = t/3; bright: gray in [0.75, 1.0]  <=> t in [2.25, 3.0]
        nb += (t0 >= 2.25f && t0 <= 3.0f);
        nb += (t1 >= 2.25f && t1 <= 3.0f);
        nb += (t2 >= 2.25f && t2 <= 3.0f);
        nb += (t3 >= 2.25f && t3 <= 3.0f);
        // dark: gray in [0, 0.25)  <=> t in [0, 0.75)
        nd += (t0 >= 0.0f && t0 < 0.75f);
        nd += (t1 >= 0.0f && t1 < 0.75f);
        nd += (t2 >= 0.0f && t2 < 0.75f);
        nd += (t3 >= 0.0f && t3 < 0.75f);

        a0 = a1; b0 = b1; v0 = v1;
    }

    // Warp reduce
    #pragma unroll
    for (int o = 16; o > 0; o >>= 1) {
        sum += __shfl_down_sync(0xFFFFFFFFu, sum, o);
        nb  += __shfl_down_sync(0xFFFFFFFFu, nb, o);
        nd  += __shfl_down_sync(0xFFFFFFFFu, nd, o);
    }

    // Block reduce across 8 warps
    __shared__ float ssum[TPB/32];
    __shared__ int   sbr[TPB/32], sdk[TPB/32];
    __shared__ int   s_is_last;
    __shared__ float s_bl, s_gl;
    const int wid  = threadIdx.x >> 5;
    const int lane = threadIdx.x & 31;
    if (lane == 0) { ssum[wid] = sum; sbr[wid] = nb; sdk[wid] = nd; }
    __syncthreads();
    if (wid == 0) {
        float s = (lane < TPB/32) ? ssum[lane] : 0.0f;
        int b_ = (lane < TPB/32) ? sbr[lane] : 0;
        int d_ = (lane < TPB/32) ? sdk[lane] : 0;
        #pragma unroll
        for (int o = 4; o > 0; o >>= 1) {
            s  += __shfl_down_sync(0xFFFFFFFFu, s, o);
            b_ += __shfl_down_sync(0xFFFFFFFFu, b_, o);
            d_ += __shfl_down_sync(0xFFFFFFFFu, d_, o);
        }
        if (lane == 0) {
            g_psum[blk]    = s;
            g_pbright[blk] = b_;
            g_pdark[blk]   = d_;
            __threadfence();
            int t = atomicAdd(&g_ticket_b[batch], 1);
            s_is_last = (t == BPB - 1);
        }
    }
    __syncthreads();

    if (!s_is_last) return;

    // ---- Last block of THIS batch: finalize this batch (L2-hot partials). ----
    if (wid == 0) {
        float fsum = 0.0f;
        int fb = 0, fd = 0;
        #pragma unroll
        for (int i = lane; i < BPB; i += 32) {
            fsum += g_psum[batch * BPB + i];
            fb   += g_pbright[batch * BPB + i];
            fd   += g_pdark[batch * BPB + i];
        }
        #pragma unroll
        for (int o = 16; o > 0; o >>= 1) {
            fsum += __shfl_down_sync(0xFFFFFFFFu, fsum, o);
            fb   += __shfl_down_sync(0xFFFFFFFFu, fb, o);
            fd   += __shfl_down_sync(0xFFFFFFFFu, fd, o);
        }
        if (lane == 0) {
            float dr   = (float)fb / ((float)fd + 1e-5f);
            float bavg = fsum * (1.0f / (3.0f * (float)HW));
            float g = 0.5f;
            float gap;
            if (dr > 1.0f && bavg > 0.4f && bavg < 0.6f)       gap = g * 2.0f;
            else if (bavg <= 0.3f)                             gap = g * 0.5f;
            else if (bavg >= 0.7f)                             gap = g * 0.5f;
            else if (dr <= 1.0f && bavg > 0.3f && bavg < 0.7f) gap = g * 0.75f;
            else                                               gap = 0.0f;
            out[0 * NB + batch] = dr;
            out[1 * NB + batch] = bavg;
            out[2 * NB + batch] = gap;
            s_bl = bavg;
            s_gl = gap;
            g_ticket_b[batch] = 0;   // reset for next graph replay
        }
    }
    __syncthreads();

    // Epilogue depends ONLY on the last batch's scalars — the batch-15
    // finalizer computes all of e1/e2 itself. No global serialization.
    if (batch == NB - 1 && threadIdx.x < NB) {
        const int bb = threadIdx.x;
        const float bl = s_bl;
        const float gl = s_gl;
        const float sc = 1.7f;
        float e1, e2;
        if (bl <= 0.25f) {
            e1 = e1in[bb] + 0.5f * gl * sc;
            e2 = e2in[bb] + 0.5f * gl * sc;
        } else if (bl >= 0.75f) {
            e1 = e1in[bb] - 0.5f * gl * sc;
            e2 = e2in[bb] - 0.5f * gl * sc;
        } else {
            e1 = e1in[bb] - 0.3f * gl;
            e2 = e2in[bb] + 0.7f * gl;
        }
        out[3 * NB + bb] = e1;
        out[4 * NB + bb] = e2;
    }
}

extern "C" void kernel_launch(void* const* d_in, const int* in_sizes, int n_in,
                              void* d_out, int out_size) {
    const float* img  = (const float*)d_in[0];
    const float* e1in = (const float*)d_in[1];
    const float* e2in = (const float*)d_in[2];
    float* out = (float*)d_out;

    fused_kernel<<<NB * BPB, TPB>>>(img, e1in, e2in, out);
}